// round 15
// baseline (speedup 1.0000x reference)
#include <cuda_runtime.h>
#include <cuda_fp16.h>
#include <cstdint>

#define BB 16
#define NN 2048
#define MM 2048
#define DD 128

// ---------------- scratch (__device__ globals: allocation-free rule) --------
__device__ __align__(16) float g_Qsq[BB * NN];
__device__ __align__(16) float g_Ksq[BB * MM];
__device__ __align__(16) uint8_t g_Q8[(size_t)BB * NN * DD];    // e4m3 [b,n,d]
__device__ __align__(16) uint8_t g_KT8[(size_t)BB * MM * DD];   // e4m3 [b,m,d]

// ---------------- helpers ---------------------------------------------------
__device__ __forceinline__ uint32_t smem_u32(const void* p) {
    uint32_t a;
    asm("{ .reg .u64 t; cvta.to.shared.u64 t, %1; cvt.u32.u64 %0, t; }"
        : "=r"(a) : "l"(p));
    return a;
}
__device__ __forceinline__ uint16_t f2_e4m3x2(float hi, float lo) {
    uint16_t r;
    asm("cvt.rn.satfinite.e4m3x2.f32 %0, %1, %2;" : "=h"(r) : "f"(hi), "f"(lo));
    return r;
}
__device__ __forceinline__ void ldsm4(uint32_t* r, uint32_t addr) {
    asm volatile("ldmatrix.sync.aligned.m8n8.x4.shared.b16 {%0,%1,%2,%3}, [%4];"
                 : "=r"(r[0]), "=r"(r[1]), "=r"(r[2]), "=r"(r[3]) : "r"(addr));
}
__device__ __forceinline__ void mma_fp8(float* c, const uint32_t* a,
                                        const uint32_t* b) {
    asm volatile(
        "mma.sync.aligned.m16n8k32.row.col.f32.e4m3.e4m3.f32 "
        "{%0,%1,%2,%3}, {%4,%5,%6,%7}, {%8,%9}, {%0,%1,%2,%3};"
        : "+f"(c[0]), "+f"(c[1]), "+f"(c[2]), "+f"(c[3])
        : "r"(a[0]), "r"(a[1]), "r"(a[2]), "r"(a[3]), "r"(b[0]), "r"(b[1]));
}
__device__ __forceinline__ float ex2a(float x) {
    float y;
    asm("ex2.approx.f32 %0, %1;" : "=f"(y) : "f"(x));
    return y;
}
__device__ __forceinline__ void stcs2(float* p, float x, float y) {
    asm volatile("st.global.cs.v2.f32 [%0], {%1, %2};" :: "l"(p), "f"(x), "f"(y)
                 : "memory");
}

// ---------------------------------------------------------------------------
// Merged prepass. Blocks [0, 4096): Q -> e4m3 + ||q||^2 (one warp per row).
// Blocks [4096, 5120): KV -> transpose to e4m3 [b,m,d] + ||k||^2.
// ---------------------------------------------------------------------------
__global__ void prep(const float* __restrict__ Q, const float* __restrict__ KV) {
    __shared__ float s[128][33];
    __shared__ float csq[256];
    const int t = threadIdx.x;

    if (blockIdx.x < 4096) {
        int row  = blockIdx.x * 8 + (t >> 5);
        int lane = t & 31;
        float4 v = reinterpret_cast<const float4*>(Q + (size_t)row * DD)[lane];
        float sum = v.x * v.x + v.y * v.y + v.z * v.z + v.w * v.w;
        uint32_t pk = (uint32_t)f2_e4m3x2(v.y, v.x)
                    | ((uint32_t)f2_e4m3x2(v.w, v.z) << 16);
        reinterpret_cast<uint32_t*>(g_Q8 + (size_t)row * DD)[lane] = pk;
#pragma unroll
        for (int o = 16; o > 0; o >>= 1) sum += __shfl_xor_sync(0xffffffffu, sum, o);
        if (lane == 0) g_Qsq[row] = sum;
        return;
    }

    const int bid = blockIdx.x - 4096;
    const int b  = bid >> 6;
    const int m0 = (bid & 63) * 32;
    const int mi = t & 31, dg = t >> 5;
    const float* base = KV + (size_t)b * DD * MM + m0;
    float acc = 0.f;
#pragma unroll
    for (int i = 0; i < 16; i++) {
        int d = i * 8 + dg;
        float v = base[(size_t)d * MM + mi];
        s[d][mi] = v;
        acc = fmaf(v, v, acc);
    }
    csq[t] = acc;
    __syncthreads();
    if (t < 32) {
        float a2 = 0.f;
#pragma unroll
        for (int j = 0; j < 8; j++) a2 += csq[t + j * 32];
        g_Ksq[(size_t)b * MM + m0 + t] = a2;
    }
#pragma unroll
    for (int it = 0; it < 2; it++) {
        int idx = it * 256 + t;
        int m = idx >> 4, kc = idx & 15, d0 = kc * 8;
        uint32_t lo = (uint32_t)f2_e4m3x2(s[d0 + 1][m], s[d0 + 0][m])
                    | ((uint32_t)f2_e4m3x2(s[d0 + 3][m], s[d0 + 2][m]) << 16);
        uint32_t hi = (uint32_t)f2_e4m3x2(s[d0 + 5][m], s[d0 + 4][m])
                    | ((uint32_t)f2_e4m3x2(s[d0 + 7][m], s[d0 + 6][m]) << 16);
        *reinterpret_cast<uint2*>(g_KT8 + ((size_t)b * MM + m0 + m) * DD + d0) =
            make_uint2(lo, hi);
    }
}

// ---------------------------------------------------------------------------
// Main kernel: SAME 128x128 tile / CTA count / traffic as the 80.3us R13
// kernel, but 512 threads (16 warps, 4x4 warp grid, 32x32 warp tile).
// Per-thread state halves (acc 32 floats), fits __launch_bounds__(512,2)
// -> 32 resident warps/SM (2x every prior round) at unchanged L2/DRAM load.
// Smem tiles: 128 rows x 128B pitch; 16B chunks swizzled by (kc ^ (row & 7)).
// ---------------------------------------------------------------------------
#define SM_A 0
#define SM_B 16384
#define SMEM_TOTAL 32768
#define L2E 1.4426950408889634f

__global__ void __launch_bounds__(512, 2)
gauss_mma(const float* __restrict__ LS, float* __restrict__ OUT) {
    extern __shared__ char smem[];
    const uint32_t sb = smem_u32(smem);
    const int t = threadIdx.x, wid = t >> 5, lane = t & 31;
    const int b = blockIdx.z, n0 = blockIdx.y * 128, m0 = blockIdx.x * 128;

    // ---- bulk load the 2 operand tiles into swizzled smem ----
    {
        const uint8_t* sA = g_Q8 + ((size_t)b * NN + n0) * DD;
#pragma unroll
        for (int i = 0; i < 2; i++) {
            int idx = i * 512 + t;
            int row = idx >> 3, kc = idx & 7;
            uint4 v = *reinterpret_cast<const uint4*>(sA + (size_t)row * DD + kc * 16);
            *reinterpret_cast<uint4*>(
                smem + SM_A + row * 128 + ((kc ^ (row & 7)) << 4)) = v;
        }
        const uint8_t* sB = g_KT8 + ((size_t)b * MM + m0) * DD;
#pragma unroll
        for (int i = 0; i < 2; i++) {
            int idx = i * 512 + t;
            int row = idx >> 3, kc = idx & 7;
            uint4 v = *reinterpret_cast<const uint4*>(sB + (size_t)row * DD + kc * 16);
            *reinterpret_cast<uint4*>(
                smem + SM_B + row * 128 + ((kc ^ (row & 7)) << 4)) = v;
        }
    }
    __syncthreads();

    // ---- fragment addressing: 4(row) x 4(col) warp grid, 32x32 warp tile ----
    const int warp_r = wid & 3;        // 0..3 -> 32 out-rows each
    const int warp_c = wid >> 2;       // 0..3 -> 32 out-cols each
    const int rmask = lane & 7;

    const int cA = lane >> 4;
    uint32_t arow_base[2];
#pragma unroll
    for (int rt = 0; rt < 2; rt++)
        arow_base[rt] = (uint32_t)((warp_r * 32 + rt * 16 + (lane & 7) +
                                    (((lane >> 3) & 1) << 3)) * 128);
    const int cB = (lane >> 3) & 1;
    uint32_t bcol_base[2];
#pragma unroll
    for (int p = 0; p < 2; p++)
        bcol_base[p] = (uint32_t)((warp_c * 32 + p * 16 + (lane & 7) +
                                   ((lane >> 4) << 3)) * 128);

    float acc[2][4][4];
#pragma unroll
    for (int rt = 0; rt < 2; rt++)
#pragma unroll
        for (int ct = 0; ct < 4; ct++)
#pragma unroll
            for (int j = 0; j < 4; j++) acc[rt][ct][j] = 0.f;

    // ---- main MMA loop: 4 k-steps (k32 each), single e4m3 pass ----
#pragma unroll
    for (int ks = 0; ks < 4; ks++) {
        uint32_t a[2][4], bf[2][4];
        uint32_t aswz = (uint32_t)((((ks << 1) + cA) ^ rmask) << 4);
#pragma unroll
        for (int rt = 0; rt < 2; rt++)
            ldsm4(a[rt], sb + SM_A + arow_base[rt] + aswz);
        uint32_t bswz = (uint32_t)((((ks << 1) + cB) ^ rmask) << 4);
#pragma unroll
        for (int p = 0; p < 2; p++)
            ldsm4(bf[p], sb + SM_B + bcol_base[p] + bswz);

#pragma unroll
        for (int rt = 0; rt < 2; rt++)
#pragma unroll
            for (int ct = 0; ct < 4; ct++)
                mma_fp8(acc[rt][ct], a[rt], bf[ct >> 1] + 2 * (ct & 1));
    }

    // ---- fused Gaussian epilogue (exp2-folded constants, static offsets) ----
    const float cc   = -0.5f * ex2a(-2.0f * LS[0] * L2E);   // -0.5/exp(2 ls)
    const float ccl  = cc * L2E;
    const float m2cl = -2.0f * ccl;

    const int r_base = n0 + warp_r * 32;
    const int c_base = m0 + warp_c * 32;
    float cq[2][2], ck[4][2];
#pragma unroll
    for (int rt = 0; rt < 2; rt++)
#pragma unroll
        for (int h = 0; h < 2; h++)
            cq[rt][h] = ccl * __ldg(&g_Qsq[(size_t)b * NN + r_base + rt * 16 +
                                           (lane >> 2) + h * 8]);
#pragma unroll
    for (int ct = 0; ct < 4; ct++)
#pragma unroll
        for (int j = 0; j < 2; j++)
            ck[ct][j] = ccl * __ldg(&g_Ksq[(size_t)b * MM + c_base + ct * 8 +
                                           2 * (lane & 3) + j]);

    float* obase = OUT + ((size_t)b * NN + r_base + (lane >> 2)) * MM +
                   c_base + 2 * (lane & 3);
#pragma unroll
    for (int rt = 0; rt < 2; rt++) {
#pragma unroll
        for (int ct = 0; ct < 4; ct++) {
#pragma unroll
            for (int h = 0; h < 2; h++) {
                float ox = ex2a(fmaf(m2cl, acc[rt][ct][2 * h + 0],
                                     cq[rt][h] + ck[ct][0]));
                float oy = ex2a(fmaf(m2cl, acc[rt][ct][2 * h + 1],
                                     cq[rt][h] + ck[ct][1]));
                stcs2(obase + (size_t)(rt * 16 + h * 8) * MM + ct * 8, ox, oy);
            }
        }
    }
}

// ---------------------------------------------------------------------------
extern "C" void kernel_launch(void* const* d_in, const int* in_sizes, int n_in,
                              void* d_out, int out_size) {
    const float* Q  = (const float*)d_in[0];
    const float* KV = (const float*)d_in[1];
    const float* LS = (const float*)d_in[2];
    float* OUT = (float*)d_out;

    cudaFuncSetAttribute(gauss_mma, cudaFuncAttributeMaxDynamicSharedMemorySize,
                         SMEM_TOTAL);

    prep<<<4096 + 1024, 256>>>(Q, KV);

    dim3 grid(MM / 128, NN / 128, BB);
    gauss_mma<<<grid, 512, SMEM_TOTAL>>>(LS, OUT);
}

// round 16
// speedup vs baseline: 1.2335x; 1.2335x over previous
#include <cuda_runtime.h>
#include <cuda_fp16.h>
#include <cstdint>

#define BB 16
#define NN 2048
#define MM 2048
#define DD 128

// ---------------- scratch (__device__ globals: allocation-free rule) --------
__device__ __align__(16) float g_Qsq[BB * NN];
__device__ __align__(16) float g_Ksq[BB * MM];
__device__ __align__(16) uint8_t g_Q8[(size_t)BB * NN * DD];    // e4m3 [b,n,d]
__device__ __align__(16) uint8_t g_KT8[(size_t)BB * MM * DD];   // e4m3 [b,m,d]

// ---------------- helpers ---------------------------------------------------
__device__ __forceinline__ uint32_t smem_u32(const void* p) {
    uint32_t a;
    asm("{ .reg .u64 t; cvta.to.shared.u64 t, %1; cvt.u32.u64 %0, t; }"
        : "=r"(a) : "l"(p));
    return a;
}
__device__ __forceinline__ uint16_t f2_e4m3x2(float hi, float lo) {
    uint16_t r;
    asm("cvt.rn.satfinite.e4m3x2.f32 %0, %1, %2;" : "=h"(r) : "f"(hi), "f"(lo));
    return r;
}
__device__ __forceinline__ void ldsm4(uint32_t* r, uint32_t addr) {
    asm volatile("ldmatrix.sync.aligned.m8n8.x4.shared.b16 {%0,%1,%2,%3}, [%4];"
                 : "=r"(r[0]), "=r"(r[1]), "=r"(r[2]), "=r"(r[3]) : "r"(addr));
}
__device__ __forceinline__ void mma_fp8(float* c, const uint32_t* a,
                                        const uint32_t* b) {
    asm volatile(
        "mma.sync.aligned.m16n8k32.row.col.f32.e4m3.e4m3.f32 "
        "{%0,%1,%2,%3}, {%4,%5,%6,%7}, {%8,%9}, {%0,%1,%2,%3};"
        : "+f"(c[0]), "+f"(c[1]), "+f"(c[2]), "+f"(c[3])
        : "r"(a[0]), "r"(a[1]), "r"(a[2]), "r"(a[3]), "r"(b[0]), "r"(b[1]));
}
__device__ __forceinline__ float ex2a(float x) {
    float y;
    asm("ex2.approx.f32 %0, %1;" : "=f"(y) : "f"(x));
    return y;
}
__device__ __forceinline__ void stcs2(float* p, float x, float y) {
    asm volatile("st.global.cs.v2.f32 [%0], {%1, %2};" :: "l"(p), "f"(x), "f"(y)
                 : "memory");
}

// ---------------------------------------------------------------------------
// Merged prepass. Blocks [0, 1024): KV -> transpose to e4m3 [b,m,d] + ||k||^2
// (the heavier blocks run first for better wave-tail balance).
// Blocks [1024, 5120): Q -> e4m3 + ||q||^2 (one warp per row).
// ---------------------------------------------------------------------------
__global__ void prep(const float* __restrict__ Q, const float* __restrict__ KV) {
    __shared__ float s[128][33];
    __shared__ float csq[256];
    const int t = threadIdx.x;

    if (blockIdx.x >= 1024) {
        int row  = (blockIdx.x - 1024) * 8 + (t >> 5);
        int lane = t & 31;
        float4 v = reinterpret_cast<const float4*>(Q + (size_t)row * DD)[lane];
        float sum = v.x * v.x + v.y * v.y + v.z * v.z + v.w * v.w;
        uint32_t pk = (uint32_t)f2_e4m3x2(v.y, v.x)
                    | ((uint32_t)f2_e4m3x2(v.w, v.z) << 16);
        reinterpret_cast<uint32_t*>(g_Q8 + (size_t)row * DD)[lane] = pk;
#pragma unroll
        for (int o = 16; o > 0; o >>= 1) sum += __shfl_xor_sync(0xffffffffu, sum, o);
        if (lane == 0) g_Qsq[row] = sum;
        return;
    }

    const int bid = blockIdx.x;
    const int b  = bid >> 6;
    const int m0 = (bid & 63) * 32;
    const int mi = t & 31, dg = t >> 5;
    const float* base = KV + (size_t)b * DD * MM + m0;
    float acc = 0.f;
#pragma unroll
    for (int i = 0; i < 16; i++) {
        int d = i * 8 + dg;
        float v = base[(size_t)d * MM + mi];
        s[d][mi] = v;
        acc = fmaf(v, v, acc);
    }
    csq[t] = acc;
    __syncthreads();
    if (t < 32) {
        float a2 = 0.f;
#pragma unroll
        for (int j = 0; j < 8; j++) a2 += csq[t + j * 32];
        g_Ksq[(size_t)b * MM + m0 + t] = a2;
    }
#pragma unroll
    for (int it = 0; it < 2; it++) {
        int idx = it * 256 + t;
        int m = idx >> 4, kc = idx & 15, d0 = kc * 8;
        uint32_t lo = (uint32_t)f2_e4m3x2(s[d0 + 1][m], s[d0 + 0][m])
                    | ((uint32_t)f2_e4m3x2(s[d0 + 3][m], s[d0 + 2][m]) << 16);
        uint32_t hi = (uint32_t)f2_e4m3x2(s[d0 + 5][m], s[d0 + 4][m])
                    | ((uint32_t)f2_e4m3x2(s[d0 + 7][m], s[d0 + 6][m]) << 16);
        *reinterpret_cast<uint2*>(g_KT8 + ((size_t)b * MM + m0 + m) * DD + d0) =
            make_uint2(lo, hi);
    }
}

// ---------------------------------------------------------------------------
// Main kernel: the measured-best R13 configuration (gauss 80.26us), verbatim.
// 128x128 tile per CTA, 8 warps (2x4 grid), ldmatrix + mma.sync e4m3 single
// pass, fp32 accumulate, exp2-folded epilogue with one obase pointer and
// immediate-offset .cs stores.
// Smem tiles: 128 rows x 128B pitch; 16B chunks swizzled by (kc ^ (row & 7)).
// ---------------------------------------------------------------------------
#define SM_A 0
#define SM_B 16384
#define SMEM_TOTAL 32768
#define L2E 1.4426950408889634f

__global__ void __launch_bounds__(256, 2)
gauss_mma(const float* __restrict__ LS, float* __restrict__ OUT) {
    extern __shared__ char smem[];
    const uint32_t sb = smem_u32(smem);
    const int t = threadIdx.x, wid = t >> 5, lane = t & 31;
    const int b = blockIdx.z, n0 = blockIdx.y * 128, m0 = blockIdx.x * 128;

    // ---- bulk load the 2 operand tiles into swizzled smem ----
    {
        const uint8_t* sA = g_Q8 + ((size_t)b * NN + n0) * DD;
#pragma unroll
        for (int i = 0; i < 4; i++) {
            int idx = i * 256 + t;
            int row = idx >> 3, kc = idx & 7;
            uint4 v = *reinterpret_cast<const uint4*>(sA + (size_t)row * DD + kc * 16);
            *reinterpret_cast<uint4*>(
                smem + SM_A + row * 128 + ((kc ^ (row & 7)) << 4)) = v;
        }
        const uint8_t* sB = g_KT8 + ((size_t)b * MM + m0) * DD;
#pragma unroll
        for (int i = 0; i < 4; i++) {
            int idx = i * 256 + t;
            int row = idx >> 3, kc = idx & 7;
            uint4 v = *reinterpret_cast<const uint4*>(sB + (size_t)row * DD + kc * 16);
            *reinterpret_cast<uint4*>(
                smem + SM_B + row * 128 + ((kc ^ (row & 7)) << 4)) = v;
        }
    }
    __syncthreads();

    // ---- fragment addressing ----
    const int warp_r = wid & 1;        // 0..1 -> 64 out-rows each
    const int warp_c = wid >> 1;       // 0..3 -> 32 out-cols each
    const int rmask = lane & 7;

    const int cA = lane >> 4;
    uint32_t arow_base[4];
#pragma unroll
    for (int rt = 0; rt < 4; rt++)
        arow_base[rt] = (uint32_t)((warp_r * 64 + rt * 16 + (lane & 7) +
                                    (((lane >> 3) & 1) << 3)) * 128);
    const int cB = (lane >> 3) & 1;
    uint32_t bcol_base[2];
#pragma unroll
    for (int p = 0; p < 2; p++)
        bcol_base[p] = (uint32_t)((warp_c * 32 + p * 16 + (lane & 7) +
                                   ((lane >> 4) << 3)) * 128);

    float acc[4][4][4];
#pragma unroll
    for (int rt = 0; rt < 4; rt++)
#pragma unroll
        for (int ct = 0; ct < 4; ct++)
#pragma unroll
            for (int j = 0; j < 4; j++) acc[rt][ct][j] = 0.f;

    // ---- main MMA loop: 4 k-steps (k32 each), single e4m3 pass ----
#pragma unroll
    for (int ks = 0; ks < 4; ks++) {
        uint32_t a[4][4], bf[2][4];
        uint32_t aswz = (uint32_t)((((ks << 1) + cA) ^ rmask) << 4);
#pragma unroll
        for (int rt = 0; rt < 4; rt++)
            ldsm4(a[rt], sb + SM_A + arow_base[rt] + aswz);
        uint32_t bswz = (uint32_t)((((ks << 1) + cB) ^ rmask) << 4);
#pragma unroll
        for (int p = 0; p < 2; p++)
            ldsm4(bf[p], sb + SM_B + bcol_base[p] + bswz);

#pragma unroll
        for (int rt = 0; rt < 4; rt++)
#pragma unroll
            for (int ct = 0; ct < 4; ct++)
                mma_fp8(acc[rt][ct], a[rt], bf[ct >> 1] + 2 * (ct & 1));
    }

    // ---- fused Gaussian epilogue (exp2-folded constants, static offsets) ----
    const float cc   = -0.5f * ex2a(-2.0f * LS[0] * L2E);   // -0.5/exp(2 ls)
    const float ccl  = cc * L2E;
    const float m2cl = -2.0f * ccl;

    const int r_base = n0 + warp_r * 64;
    const int c_base = m0 + warp_c * 32;
    float cq[4][2], ck[4][2];
#pragma unroll
    for (int rt = 0; rt < 4; rt++)
#pragma unroll
        for (int h = 0; h < 2; h++)
            cq[rt][h] = ccl * __ldg(&g_Qsq[(size_t)b * NN + r_base + rt * 16 +
                                           (lane >> 2) + h * 8]);
#pragma unroll
    for (int ct = 0; ct < 4; ct++)
#pragma unroll
        for (int j = 0; j < 2; j++)
            ck[ct][j] = ccl * __ldg(&g_Ksq[(size_t)b * MM + c_base + ct * 8 +
                                           2 * (lane & 3) + j]);

    float* obase = OUT + ((size_t)b * NN + r_base + (lane >> 2)) * MM +
                   c_base + 2 * (lane & 3);
#pragma unroll
    for (int rt = 0; rt < 4; rt++) {
#pragma unroll
        for (int ct = 0; ct < 4; ct++) {
#pragma unroll
            for (int h = 0; h < 2; h++) {
                float ox = ex2a(fmaf(m2cl, acc[rt][ct][2 * h + 0],
                                     cq[rt][h] + ck[ct][0]));
                float oy = ex2a(fmaf(m2cl, acc[rt][ct][2 * h + 1],
                                     cq[rt][h] + ck[ct][1]));
                stcs2(obase + (size_t)(rt * 16 + h * 8) * MM + ct * 8, ox, oy);
            }
        }
    }
}

// ---------------------------------------------------------------------------
extern "C" void kernel_launch(void* const* d_in, const int* in_sizes, int n_in,
                              void* d_out, int out_size) {
    const float* Q  = (const float*)d_in[0];
    const float* KV = (const float*)d_in[1];
    const float* LS = (const float*)d_in[2];
    float* OUT = (float*)d_out;

    cudaFuncSetAttribute(gauss_mma, cudaFuncAttributeMaxDynamicSharedMemorySize,
                         SMEM_TOTAL);

    prep<<<4096 + 1024, 256>>>(Q, KV);

    dim3 grid(MM / 128, NN / 128, BB);
    gauss_mma<<<grid, 256, SMEM_TOTAL>>>(LS, OUT);
}

// round 17
// speedup vs baseline: 1.3175x; 1.0681x over previous
#include <cuda_runtime.h>
#include <cuda_fp16.h>
#include <cstdint>

#define BB 16
#define NN 2048
#define MM 2048
#define DD 128

// ---------------- scratch (__device__ globals: allocation-free rule) --------
__device__ __align__(16) float g_Qsq[BB * NN];
__device__ __align__(16) float g_Ksq[BB * MM];
__device__ __align__(16) uint8_t g_Q8[(size_t)BB * NN * DD];    // e4m3 [b,n,d]
__device__ __align__(16) uint8_t g_KT8[(size_t)BB * MM * DD];   // e4m3 [b,m,d]

// ---------------- helpers ---------------------------------------------------
__device__ __forceinline__ uint32_t smem_u32(const void* p) {
    uint32_t a;
    asm("{ .reg .u64 t; cvta.to.shared.u64 t, %1; cvt.u32.u64 %0, t; }"
        : "=r"(a) : "l"(p));
    return a;
}
__device__ __forceinline__ uint16_t f2_e4m3x2(float hi, float lo) {
    uint16_t r;
    asm("cvt.rn.satfinite.e4m3x2.f32 %0, %1, %2;" : "=h"(r) : "f"(hi), "f"(lo));
    return r;
}
__device__ __forceinline__ void ldsm4(uint32_t* r, uint32_t addr) {
    asm volatile("ldmatrix.sync.aligned.m8n8.x4.shared.b16 {%0,%1,%2,%3}, [%4];"
                 : "=r"(r[0]), "=r"(r[1]), "=r"(r[2]), "=r"(r[3]) : "r"(addr));
}
__device__ __forceinline__ void mma_fp8(float* c, const uint32_t* a,
                                        const uint32_t* b) {
    asm volatile(
        "mma.sync.aligned.m16n8k32.row.col.f32.e4m3.e4m3.f32 "
        "{%0,%1,%2,%3}, {%4,%5,%6,%7}, {%8,%9}, {%0,%1,%2,%3};"
        : "+f"(c[0]), "+f"(c[1]), "+f"(c[2]), "+f"(c[3])
        : "r"(a[0]), "r"(a[1]), "r"(a[2]), "r"(a[3]), "r"(b[0]), "r"(b[1]));
}
__device__ __forceinline__ float ex2a(float x) {
    float y;
    asm("ex2.approx.f32 %0, %1;" : "=f"(y) : "f"(x));
    return y;
}
// packed exp2 of two fp32 args via bf16x2 (1 MUFU for 2 values; ALU unpack)
__device__ __forceinline__ void ex2_pair_bf16(float& ox, float& oy,
                                              float ax, float ay) {
    uint32_t packed, e2;
    asm("cvt.rn.bf16x2.f32 %0, %1, %2;" : "=r"(packed) : "f"(ay), "f"(ax));
    asm("ex2.approx.ftz.bf16x2 %0, %1;" : "=r"(e2) : "r"(packed));
    ox = __uint_as_float(e2 << 16);            // low half -> exp2(ax)
    oy = __uint_as_float(e2 & 0xffff0000u);    // high half -> exp2(ay)
}
__device__ __forceinline__ void stcs2(float* p, float x, float y) {
    asm volatile("st.global.cs.v2.f32 [%0], {%1, %2};" :: "l"(p), "f"(x), "f"(y)
                 : "memory");
}

// ---------------------------------------------------------------------------
// Merged prepass. Blocks [0, 1024): KV -> transpose to e4m3 [b,m,d] + ||k||^2
// (heavier blocks first for wave-tail balance).
// Blocks [1024, 5120): Q -> e4m3 + ||q||^2 (one warp per row).
// ---------------------------------------------------------------------------
__global__ void prep(const float* __restrict__ Q, const float* __restrict__ KV) {
    __shared__ float s[128][33];
    __shared__ float csq[256];
    const int t = threadIdx.x;

    if (blockIdx.x >= 1024) {
        int row  = (blockIdx.x - 1024) * 8 + (t >> 5);
        int lane = t & 31;
        float4 v = reinterpret_cast<const float4*>(Q + (size_t)row * DD)[lane];
        float sum = v.x * v.x + v.y * v.y + v.z * v.z + v.w * v.w;
        uint32_t pk = (uint32_t)f2_e4m3x2(v.y, v.x)
                    | ((uint32_t)f2_e4m3x2(v.w, v.z) << 16);
        reinterpret_cast<uint32_t*>(g_Q8 + (size_t)row * DD)[lane] = pk;
#pragma unroll
        for (int o = 16; o > 0; o >>= 1) sum += __shfl_xor_sync(0xffffffffu, sum, o);
        if (lane == 0) g_Qsq[row] = sum;
        return;
    }

    const int bid = blockIdx.x;
    const int b  = bid >> 6;
    const int m0 = (bid & 63) * 32;
    const int mi = t & 31, dg = t >> 5;
    const float* base = KV + (size_t)b * DD * MM + m0;
    float acc = 0.f;
#pragma unroll
    for (int i = 0; i < 16; i++) {
        int d = i * 8 + dg;
        float v = base[(size_t)d * MM + mi];
        s[d][mi] = v;
        acc = fmaf(v, v, acc);
    }
    csq[t] = acc;
    __syncthreads();
    if (t < 32) {
        float a2 = 0.f;
#pragma unroll
        for (int j = 0; j < 8; j++) a2 += csq[t + j * 32];
        g_Ksq[(size_t)b * MM + m0 + t] = a2;
    }
#pragma unroll
    for (int it = 0; it < 2; it++) {
        int idx = it * 256 + t;
        int m = idx >> 4, kc = idx & 15, d0 = kc * 8;
        uint32_t lo = (uint32_t)f2_e4m3x2(s[d0 + 1][m], s[d0 + 0][m])
                    | ((uint32_t)f2_e4m3x2(s[d0 + 3][m], s[d0 + 2][m]) << 16);
        uint32_t hi = (uint32_t)f2_e4m3x2(s[d0 + 5][m], s[d0 + 4][m])
                    | ((uint32_t)f2_e4m3x2(s[d0 + 7][m], s[d0 + 6][m]) << 16);
        *reinterpret_cast<uint2*>(g_KT8 + ((size_t)b * MM + m0 + m) * DD + d0) =
            make_uint2(lo, hi);
    }
}

// ---------------------------------------------------------------------------
// Main kernel: R15 structure (measured best). Sole change: epilogue exp2 is
// computed pairwise via ex2.approx.ftz.bf16x2 — halves the MUFU/XU lane
// count (the hidden ~73%-utilized pipe), unpack is pure ALU (shift/mask).
// Smem tiles: 128 rows x 128B pitch; 16B chunks swizzled by (kc ^ (row & 7)).
// ---------------------------------------------------------------------------
#define SM_A 0
#define SM_B 16384
#define SMEM_TOTAL 32768
#define L2E 1.4426950408889634f

__global__ void __launch_bounds__(256, 2)
gauss_mma(const float* __restrict__ LS, float* __restrict__ OUT) {
    extern __shared__ char smem[];
    const uint32_t sb = smem_u32(smem);
    const int t = threadIdx.x, wid = t >> 5, lane = t & 31;
    const int b = blockIdx.z, n0 = blockIdx.y * 128, m0 = blockIdx.x * 128;

    // ---- bulk load the 2 operand tiles into swizzled smem ----
    {
        const uint8_t* sA = g_Q8 + ((size_t)b * NN + n0) * DD;
#pragma unroll
        for (int i = 0; i < 4; i++) {
            int idx = i * 256 + t;
            int row = idx >> 3, kc = idx & 7;
            uint4 v = *reinterpret_cast<const uint4*>(sA + (size_t)row * DD + kc * 16);
            *reinterpret_cast<uint4*>(
                smem + SM_A + row * 128 + ((kc ^ (row & 7)) << 4)) = v;
        }
        const uint8_t* sB = g_KT8 + ((size_t)b * MM + m0) * DD;
#pragma unroll
        for (int i = 0; i < 4; i++) {
            int idx = i * 256 + t;
            int row = idx >> 3, kc = idx & 7;
            uint4 v = *reinterpret_cast<const uint4*>(sB + (size_t)row * DD + kc * 16);
            *reinterpret_cast<uint4*>(
                smem + SM_B + row * 128 + ((kc ^ (row & 7)) << 4)) = v;
        }
    }
    __syncthreads();

    // ---- fragment addressing ----
    const int warp_r = wid & 1;        // 0..1 -> 64 out-rows each
    const int warp_c = wid >> 1;       // 0..3 -> 32 out-cols each
    const int rmask = lane & 7;

    const int cA = lane >> 4;
    uint32_t arow_base[4];
#pragma unroll
    for (int rt = 0; rt < 4; rt++)
        arow_base[rt] = (uint32_t)((warp_r * 64 + rt * 16 + (lane & 7) +
                                    (((lane >> 3) & 1) << 3)) * 128);
    const int cB = (lane >> 3) & 1;
    uint32_t bcol_base[2];
#pragma unroll
    for (int p = 0; p < 2; p++)
        bcol_base[p] = (uint32_t)((warp_c * 32 + p * 16 + (lane & 7) +
                                   ((lane >> 4) << 3)) * 128);

    float acc[4][4][4];
#pragma unroll
    for (int rt = 0; rt < 4; rt++)
#pragma unroll
        for (int ct = 0; ct < 4; ct++)
#pragma unroll
            for (int j = 0; j < 4; j++) acc[rt][ct][j] = 0.f;

    // ---- main MMA loop: 4 k-steps (k32 each), single e4m3 pass ----
#pragma unroll
    for (int ks = 0; ks < 4; ks++) {
        uint32_t a[4][4], bf[2][4];
        uint32_t aswz = (uint32_t)((((ks << 1) + cA) ^ rmask) << 4);
#pragma unroll
        for (int rt = 0; rt < 4; rt++)
            ldsm4(a[rt], sb + SM_A + arow_base[rt] + aswz);
        uint32_t bswz = (uint32_t)((((ks << 1) + cB) ^ rmask) << 4);
#pragma unroll
        for (int p = 0; p < 2; p++)
            ldsm4(bf[p], sb + SM_B + bcol_base[p] + bswz);

#pragma unroll
        for (int rt = 0; rt < 4; rt++)
#pragma unroll
            for (int ct = 0; ct < 4; ct++)
                mma_fp8(acc[rt][ct], a[rt], bf[ct >> 1] + 2 * (ct & 1));
    }

    // ---- fused Gaussian epilogue (exp2-folded constants, bf16x2 EX2) ----
    const float cc   = -0.5f * ex2a(-2.0f * LS[0] * L2E);   // -0.5/exp(2 ls)
    const float ccl  = cc * L2E;
    const float m2cl = -2.0f * ccl;

    const int r_base = n0 + warp_r * 64;
    const int c_base = m0 + warp_c * 32;
    float cq[4][2], ck[4][2];
#pragma unroll
    for (int rt = 0; rt < 4; rt++)
#pragma unroll
        for (int h = 0; h < 2; h++)
            cq[rt][h] = ccl * __ldg(&g_Qsq[(size_t)b * NN + r_base + rt * 16 +
                                           (lane >> 2) + h * 8]);
#pragma unroll
    for (int ct = 0; ct < 4; ct++)
#pragma unroll
        for (int j = 0; j < 2; j++)
            ck[ct][j] = ccl * __ldg(&g_Ksq[(size_t)b * MM + c_base + ct * 8 +
                                           2 * (lane & 3) + j]);

    float* obase = OUT + ((size_t)b * NN + r_base + (lane >> 2)) * MM +
                   c_base + 2 * (lane & 3);
#pragma unroll
    for (int rt = 0; rt < 4; rt++) {
#pragma unroll
        for (int ct = 0; ct < 4; ct++) {
#pragma unroll
            for (int h = 0; h < 2; h++) {
                float ax = fmaf(m2cl, acc[rt][ct][2 * h + 0],
                                cq[rt][h] + ck[ct][0]);
                float ay = fmaf(m2cl, acc[rt][ct][2 * h + 1],
                                cq[rt][h] + ck[ct][1]);
                float ox, oy;
                ex2_pair_bf16(ox, oy, ax, ay);
                stcs2(obase + (size_t)(rt * 16 + h * 8) * MM + ct * 8, ox, oy);
            }
        }
    }
}

// ---------------------------------------------------------------------------
extern "C" void kernel_launch(void* const* d_in, const int* in_sizes, int n_in,
                              void* d_out, int out_size) {
    const float* Q  = (const float*)d_in[0];
    const float* KV = (const float*)d_in[1];
    const float* LS = (const float*)d_in[2];
    float* OUT = (float*)d_out;

    cudaFuncSetAttribute(gauss_mma, cudaFuncAttributeMaxDynamicSharedMemorySize,
                         SMEM_TOTAL);

    prep<<<4096 + 1024, 256>>>(Q, KV);

    dim3 grid(MM / 128, NN / 128, BB);
    gauss_mma<<<grid, 256, SMEM_TOTAL>>>(LS, OUT);
}